// round 1
// baseline (speedup 1.0000x reference)
#include <cuda_runtime.h>
#include <cstdint>

// GAGKNNQueryAndGroup on GB300.
// Key observation: LAMBDA = 0.5 -> lam == 1-lam == 0.5, so the component-aware
// rescale multiplies EVERY distance by exactly 0.5 (exact in fp32). Ordering is
// plain squared-distance KNN; components inputs are dead.
//
// Kernel 1 (knn): warp per query. Points staged in shared memory as SoA
// (x[],y[],z[]), 8 queries per block amortize the load. Each warp maintains its
// current best-32 as a sorted list distributed one element per lane
// (lane 0 = nearest). Key = (dist_bits << 32) | point_idx  (stable tie-break,
// matching stable argsort). Candidates are checked against the 32nd-best
// threshold; qualifying ones are inserted via a warp ballot + shfl_up shift.
// Expected inserts/query ~ 32 + 32*ln(8192/32) ~ 210 -> cheap.
//
// Kernel 2 (gather): one block per (batch, output channel). The 8192-float
// source row (feature row, or xyz component) is staged in smem; output writes
// are fully coalesced. Avoids the 32KB-strided scatter reads a fused gather
// would incur.

#define FULLMASK 0xffffffffu

constexpr int BATCH  = 4;
constexpr int NPTS   = 8192;
constexpr int NQUERY = 2048;
constexpr int NCH    = 64;
constexpr int NS     = 32;
constexpr int QPB    = 8;     // queries (warps) per block in knn kernel
constexpr int KNN_THREADS = QPB * 32;

__device__ int g_knn_idx[BATCH * NQUERY * NS];

__device__ __forceinline__ float sqdist(float qx, float qy, float qz,
                                        float x, float y, float z) {
    // Deliberately no FMA contraction: mul each diff, then left-to-right sum,
    // tracking the reference's elementwise (diff*diff) + reduce over axis of 3.
    float dx = qx - x, dy = qy - y, dz = qz - z;
    return __fadd_rn(__fadd_rn(__fmul_rn(dx, dx), __fmul_rn(dy, dy)),
                     __fmul_rn(dz, dz));
}

// Insert key e (< thr) into the warp-distributed ascending best list.
__device__ __forceinline__ void warp_insert(unsigned long long& best,
                                            unsigned long long& thr,
                                            unsigned long long e,
                                            int lane) {
    unsigned bal = __ballot_sync(FULLMASK, best > e);   // contiguous suffix
    int p = __ffs(bal) - 1;                             // insertion position
    unsigned long long up = __shfl_up_sync(FULLMASK, best, 1);
    if (lane >= p) best = (lane == p) ? e : up;
    thr = __shfl_sync(FULLMASK, best, 31);
}

// Process one candidate key per lane (warp-uniform control flow).
__device__ __forceinline__ void process_cand(unsigned long long k,
                                             unsigned long long& best,
                                             unsigned long long& thr,
                                             int lane) {
    unsigned q = __ballot_sync(FULLMASK, k < thr);
    while (q) {
        int src = __ffs(q) - 1;
        unsigned long long e = __shfl_sync(FULLMASK, k, src);
        warp_insert(best, thr, e, lane);
        q &= q - 1;                                    // drop consumed lane
        q &= __ballot_sync(FULLMASK, k < thr);         // re-filter vs new thr
    }
}

__global__ void knn_kernel(const float* __restrict__ xyz,
                           const float* __restrict__ new_xyz) {
    extern __shared__ float sh[];
    float* shx = sh;
    float* shy = sh + NPTS;
    float* shz = sh + 2 * NPTS;

    const int blocks_per_batch = NQUERY / QPB;
    const int b    = blockIdx.x / blocks_per_batch;
    const int qblk = blockIdx.x % blocks_per_batch;

    // Stage this batch's points into SoA shared memory (coalesced float4 reads).
    const float4* p4 = reinterpret_cast<const float4*>(xyz + (size_t)b * NPTS * 3);
    for (int j = threadIdx.x; j < NPTS * 3 / 4; j += KNN_THREADS) {
        float4 f = p4[j];
        float v[4] = {f.x, f.y, f.z, f.w};
        int flat = 4 * j;
        #pragma unroll
        for (int t = 0; t < 4; t++) {
            int p = (flat + t) / 3;
            int c = (flat + t) - 3 * p;
            float* dst = (c == 0) ? shx : (c == 1) ? shy : shz;
            dst[p] = v[t];
        }
    }
    __syncthreads();

    const int w    = threadIdx.x >> 5;
    const int lane = threadIdx.x & 31;
    const int q    = qblk * QPB + w;

    const float* nq = new_xyz + ((size_t)b * NQUERY + q) * 3;
    const float qx = nq[0], qy = nq[1], qz = nq[2];

    unsigned long long best = ~0ULL;   // sorted ascending across lanes
    unsigned long long thr  = ~0ULL;   // best[31] broadcast

    for (int base = 0; base < NPTS; base += 128) {
        const int i0 = base + lane * 4;
        float4 X = *reinterpret_cast<const float4*>(shx + i0);
        float4 Y = *reinterpret_cast<const float4*>(shy + i0);
        float4 Z = *reinterpret_cast<const float4*>(shz + i0);

        float d0 = sqdist(qx, qy, qz, X.x, Y.x, Z.x);
        float d1 = sqdist(qx, qy, qz, X.y, Y.y, Z.y);
        float d2 = sqdist(qx, qy, qz, X.z, Y.z, Z.z);
        float d3 = sqdist(qx, qy, qz, X.w, Y.w, Z.w);

        unsigned long long k0 = ((unsigned long long)__float_as_uint(d0) << 32) | (unsigned)(i0 + 0);
        unsigned long long k1 = ((unsigned long long)__float_as_uint(d1) << 32) | (unsigned)(i0 + 1);
        unsigned long long k2 = ((unsigned long long)__float_as_uint(d2) << 32) | (unsigned)(i0 + 2);
        unsigned long long k3 = ((unsigned long long)__float_as_uint(d3) << 32) | (unsigned)(i0 + 3);

        bool any = (k0 < thr) | (k1 < thr) | (k2 < thr) | (k3 < thr);
        if (__ballot_sync(FULLMASK, any)) {
            process_cand(k0, best, thr, lane);
            process_cand(k1, best, thr, lane);
            process_cand(k2, best, thr, lane);
            process_cand(k3, best, thr, lane);
        }
    }

    // lane s holds the s-th nearest neighbor (stable order).
    g_knn_idx[((size_t)b * NQUERY + q) * NS + lane] = (int)(unsigned)(best & 0xffffffffu);
}

constexpr int OUT_CH = 3 + NCH;                // 67
constexpr int ELEMS  = NQUERY * NS;            // 65536 per (b, ch)
constexpr int GATHER_THREADS = 1024;

__global__ void gather_kernel(const float* __restrict__ xyz,
                              const float* __restrict__ new_xyz,
                              const float* __restrict__ feats,
                              float* __restrict__ out) {
    __shared__ float row[NPTS];
    const int b  = blockIdx.x / OUT_CH;
    const int ch = blockIdx.x % OUT_CH;

    if (ch >= 3) {
        const float* src = feats + ((size_t)b * NCH + (ch - 3)) * NPTS;
        for (int i = threadIdx.x; i < NPTS; i += GATHER_THREADS) row[i] = src[i];
    } else {
        const float* src = xyz + (size_t)b * NPTS * 3;
        for (int i = threadIdx.x; i < NPTS; i += GATHER_THREADS) row[i] = src[i * 3 + ch];
    }
    __syncthreads();

    const int* idxb = g_knn_idx + (size_t)b * ELEMS;
    float* ob = out + ((size_t)b * OUT_CH + ch) * ELEMS;

    for (int e = threadIdx.x; e < ELEMS; e += GATHER_THREADS) {
        int n = idxb[e];
        float v = row[n];
        if (ch < 3) {
            // grouped_xyz = gathered - query  (exact fp32 sub, matches ref)
            v = __fsub_rn(v, new_xyz[((size_t)b * NQUERY + (e >> 5)) * 3 + ch]);
        }
        ob[e] = v;
    }
}

extern "C" void kernel_launch(void* const* d_in, const int* in_sizes, int n_in,
                              void* d_out, int out_size) {
    const float* xyz      = (const float*)d_in[0];   // (4, 8192, 3) f32
    const float* new_xyz  = (const float*)d_in[1];   // (4, 2048, 3) f32
    // d_in[2], d_in[3]: components / new_components (int64) -- dead (LAMBDA=0.5)
    const float* feats    = (const float*)d_in[4];   // (4, 64, 8192) f32
    float* out = (float*)d_out;                      // (4, 67, 2048, 32) f32

    const int knn_smem = 3 * NPTS * sizeof(float);   // 96 KB
    cudaFuncSetAttribute(knn_kernel, cudaFuncAttributeMaxDynamicSharedMemorySize,
                         knn_smem);

    knn_kernel<<<BATCH * (NQUERY / QPB), KNN_THREADS, knn_smem>>>(xyz, new_xyz);
    gather_kernel<<<BATCH * OUT_CH, GATHER_THREADS>>>(xyz, new_xyz, feats, out);
}

// round 2
// speedup vs baseline: 1.4346x; 1.4346x over previous
#include <cuda_runtime.h>
#include <cstdint>

// GAGKNNQueryAndGroup on GB300.
// LAMBDA = 0.5 -> lam == 1-lam, the component rescale scales all distances by
// 0.5 (exact exponent decrement): ordering is plain squared-distance KNN and
// the components inputs are dead.
//
// R2 changes vs R1 (191us):
//  - knn: QPB 8 -> 16 (512 thr/block, same 96KB smem) => 32 warps/SM instead
//    of 16; the serialized shfl insert chains are now 2x better hidden.
//  - knn: candidate filter is a single u32 compare (fp32 bits of nonneg floats
//    are monotonic as unsigned). Inclusive (<=) so boundary ties still reach
//    the exact 64-bit-key insert; stability preserved.
//  - gather: int4 idx loads + float4 stores, unroll 4 (MLP ~16/thread instead
//    of ~1); new_xyz channel staged in smem for the 3 xyz channels.

#define FULLMASK 0xffffffffu

constexpr int BATCH  = 4;
constexpr int NPTS   = 8192;
constexpr int NQUERY = 2048;
constexpr int NCH    = 64;
constexpr int NS     = 32;
constexpr int QPB    = 16;    // queries (warps) per block in knn kernel
constexpr int KNN_THREADS = QPB * 32;

__device__ int g_knn_idx[BATCH * NQUERY * NS];

__device__ __forceinline__ float sqdist(float qx, float qy, float qz,
                                        float x, float y, float z) {
    // No FMA contraction: elementwise mul then left-to-right add, matching the
    // reference's (diff*diff) + sum-over-3 ordering bit-for-bit.
    float dx = qx - x, dy = qy - y, dz = qz - z;
    return __fadd_rn(__fadd_rn(__fmul_rn(dx, dx), __fmul_rn(dy, dy)),
                     __fmul_rn(dz, dz));
}

// Insert 64-bit key e into the warp-distributed ascending best list (skip if
// e >= best[31]); refresh the u32 distance threshold.
__device__ __forceinline__ void warp_insert(unsigned long long& best,
                                            unsigned& thrBits,
                                            unsigned long long e,
                                            int lane) {
    unsigned bal = __ballot_sync(FULLMASK, best > e);   // contiguous suffix
    if (bal) {
        int p = __ffs(bal) - 1;                         // insertion position
        unsigned long long up = __shfl_up_sync(FULLMASK, best, 1);
        if (lane >= p) best = (lane == p) ? e : up;
    }
    thrBits = (unsigned)(__shfl_sync(FULLMASK, best, 31) >> 32);
}

// One candidate (dist bits u, index i) per lane; warp-uniform control flow.
__device__ __forceinline__ void process_cand(unsigned u, int i,
                                             unsigned long long& best,
                                             unsigned& thrBits,
                                             int lane) {
    unsigned q = __ballot_sync(FULLMASK, u <= thrBits);
    if (!q) return;
    unsigned long long k = ((unsigned long long)u << 32) | (unsigned)i;
    do {
        int src = __ffs(q) - 1;
        unsigned long long e = __shfl_sync(FULLMASK, k, src);
        warp_insert(best, thrBits, e, lane);
        q &= q - 1;                                     // drop consumed lane
        q &= __ballot_sync(FULLMASK, u <= thrBits);     // re-filter vs new thr
    } while (q);
}

__global__ __launch_bounds__(KNN_THREADS, 2)
void knn_kernel(const float* __restrict__ xyz,
                const float* __restrict__ new_xyz) {
    extern __shared__ float sh[];
    float* shx = sh;
    float* shy = sh + NPTS;
    float* shz = sh + 2 * NPTS;

    const int blocks_per_batch = NQUERY / QPB;
    const int b    = blockIdx.x / blocks_per_batch;
    const int qblk = blockIdx.x % blocks_per_batch;

    // Stage this batch's points into SoA shared memory (coalesced float4 reads).
    const float4* p4 = reinterpret_cast<const float4*>(xyz + (size_t)b * NPTS * 3);
    for (int j = threadIdx.x; j < NPTS * 3 / 4; j += KNN_THREADS) {
        float4 f = p4[j];
        float v[4] = {f.x, f.y, f.z, f.w};
        int flat = 4 * j;
        #pragma unroll
        for (int t = 0; t < 4; t++) {
            int p = (flat + t) / 3;
            int c = (flat + t) - 3 * p;
            float* dst = (c == 0) ? shx : (c == 1) ? shy : shz;
            dst[p] = v[t];
        }
    }
    __syncthreads();

    const int w    = threadIdx.x >> 5;
    const int lane = threadIdx.x & 31;
    const int q    = qblk * QPB + w;

    const float* nq = new_xyz + ((size_t)b * NQUERY + q) * 3;
    const float qx = nq[0], qy = nq[1], qz = nq[2];

    unsigned long long best = ~0ULL;   // sorted ascending across lanes
    unsigned thrBits = 0xffffffffu;    // dist bits of best[31]

    for (int base = 0; base < NPTS; base += 128) {
        const int i0 = base + lane * 4;   // 16B/lane stride: conflict-free LDS.128
        float4 X = *reinterpret_cast<const float4*>(shx + i0);
        float4 Y = *reinterpret_cast<const float4*>(shy + i0);
        float4 Z = *reinterpret_cast<const float4*>(shz + i0);

        unsigned u0 = __float_as_uint(sqdist(qx, qy, qz, X.x, Y.x, Z.x));
        unsigned u1 = __float_as_uint(sqdist(qx, qy, qz, X.y, Y.y, Z.y));
        unsigned u2 = __float_as_uint(sqdist(qx, qy, qz, X.z, Y.z, Z.z));
        unsigned u3 = __float_as_uint(sqdist(qx, qy, qz, X.w, Y.w, Z.w));

        bool any = (u0 <= thrBits) | (u1 <= thrBits) |
                   (u2 <= thrBits) | (u3 <= thrBits);
        if (__ballot_sync(FULLMASK, any)) {
            process_cand(u0, i0 + 0, best, thrBits, lane);
            process_cand(u1, i0 + 1, best, thrBits, lane);
            process_cand(u2, i0 + 2, best, thrBits, lane);
            process_cand(u3, i0 + 3, best, thrBits, lane);
        }
    }

    // lane s holds the s-th nearest neighbor (stable order).
    g_knn_idx[((size_t)b * NQUERY + q) * NS + lane] = (int)(unsigned)(best & 0xffffffffu);
}

constexpr int OUT_CH = 3 + NCH;                // 67
constexpr int ELEMS  = NQUERY * NS;            // 65536 per (b, ch)
constexpr int GATHER_THREADS = 1024;

__global__ __launch_bounds__(GATHER_THREADS)
void gather_kernel(const float* __restrict__ xyz,
                   const float* __restrict__ new_xyz,
                   const float* __restrict__ feats,
                   float* __restrict__ out) {
    __shared__ float row[NPTS];
    __shared__ float qrow[NQUERY];
    const int b  = blockIdx.x / OUT_CH;
    const int ch = blockIdx.x % OUT_CH;

    if (ch >= 3) {
        const float4* src = reinterpret_cast<const float4*>(
            feats + ((size_t)b * NCH + (ch - 3)) * NPTS);
        float4* dst = reinterpret_cast<float4*>(row);
        for (int i = threadIdx.x; i < NPTS / 4; i += GATHER_THREADS) dst[i] = src[i];
    } else {
        const float* src = xyz + (size_t)b * NPTS * 3;
        for (int i = threadIdx.x; i < NPTS; i += GATHER_THREADS)
            row[i] = src[i * 3 + ch];
        const float* qsrc = new_xyz + (size_t)b * NQUERY * 3;
        for (int i = threadIdx.x; i < NQUERY; i += GATHER_THREADS)
            qrow[i] = qsrc[i * 3 + ch];
    }
    __syncthreads();

    const int4* idx4 = reinterpret_cast<const int4*>(g_knn_idx + (size_t)b * ELEMS);
    float4* ob4 = reinterpret_cast<float4*>(out + ((size_t)b * OUT_CH + ch) * ELEMS);

    constexpr int NV = ELEMS / 4;   // 16384 float4s per (b, ch)
    if (ch >= 3) {
        #pragma unroll 4
        for (int e = threadIdx.x; e < NV; e += GATHER_THREADS) {
            int4 n = idx4[e];
            float4 v = make_float4(row[n.x], row[n.y], row[n.z], row[n.w]);
            ob4[e] = v;
        }
    } else {
        #pragma unroll 4
        for (int e = threadIdx.x; e < NV; e += GATHER_THREADS) {
            int4 n = idx4[e];
            float qv = qrow[e >> 3];          // query index = (4e)/32
            float4 v;
            v.x = __fsub_rn(row[n.x], qv);
            v.y = __fsub_rn(row[n.y], qv);
            v.z = __fsub_rn(row[n.z], qv);
            v.w = __fsub_rn(row[n.w], qv);
            ob4[e] = v;
        }
    }
}

extern "C" void kernel_launch(void* const* d_in, const int* in_sizes, int n_in,
                              void* d_out, int out_size) {
    const float* xyz      = (const float*)d_in[0];   // (4, 8192, 3) f32
    const float* new_xyz  = (const float*)d_in[1];   // (4, 2048, 3) f32
    // d_in[2], d_in[3]: components / new_components (int64) -- dead (LAMBDA=0.5)
    const float* feats    = (const float*)d_in[4];   // (4, 64, 8192) f32
    float* out = (float*)d_out;                      // (4, 67, 2048, 32) f32

    const int knn_smem = 3 * NPTS * sizeof(float);   // 96 KB
    cudaFuncSetAttribute(knn_kernel, cudaFuncAttributeMaxDynamicSharedMemorySize,
                         knn_smem);

    knn_kernel<<<BATCH * (NQUERY / QPB), KNN_THREADS, knn_smem>>>(xyz, new_xyz);
    gather_kernel<<<BATCH * OUT_CH, GATHER_THREADS>>>(xyz, new_xyz, feats, out);
}